// round 5
// baseline (speedup 1.0000x reference)
#include <cuda_runtime.h>
#include <cuda_bf16.h>
#include <math.h>

// Problem constants
#define B_   8
#define T_   4096
#define NH_  16
#define MD_  64
#define FF_  256
#define HEADS_ 4
#define DH_  16
#define PEH_ 32
#define BT_  (B_ * T_)        // 32768

// ---------------- packed f32x2 helpers (sm_103a FFMA2) ----------------
__device__ __forceinline__ unsigned long long pk2(float x, float y) {
    unsigned long long r;
    asm("mov.b64 %0, {%1, %2};" : "=l"(r) : "f"(x), "f"(y));
    return r;
}
__device__ __forceinline__ void fma2(unsigned long long& d,
                                     unsigned long long a, unsigned long long b) {
    asm("fma.rn.f32x2 %0, %1, %2, %0;" : "+l"(d) : "l"(a), "l"(b));
}
__device__ __forceinline__ void add2(unsigned long long& d, unsigned long long a) {
    asm("add.rn.f32x2 %0, %0, %1;" : "+l"(d) : "l"(a));
}
__device__ __forceinline__ float2 upk(unsigned long long v) {
    float lo, hi;
    asm("mov.b64 {%0, %1}, %2;" : "=f"(lo), "=f"(hi) : "l"(v));
    return make_float2(lo, hi);
}

// ---------------- device scratch (static, no allocations) ----------------
__device__ float g_xn[(size_t)BT_ * MD_];            // LN1 output       8 MB
__device__ int   g_idx[T_ * NH_];
__device__ float g_c1[T_ * NH_];
__device__ float g_c2[T_ * NH_];
__device__ float g_bias[(size_t)T_ * HEADS_ * NH_ * NH_];   // 16 MB
__device__ float g_xu[(size_t)BT_ * (NH_ * MD_)];    // LN3 output     134 MB

// =========================================================================
// Kernel 1: LayerNorm over x rows (B*T rows of 64)
// =========================================================================
__global__ void k_ln1(const float* __restrict__ x,
                      const float* __restrict__ g1,
                      const float* __restrict__ be1)
{
    int row  = blockIdx.x * 8 + (threadIdx.x >> 5);
    int lane = threadIdx.x & 31;
    const float* xr = x + (size_t)row * 64;
    float a = xr[lane], b = xr[lane + 32];
    float s = a + b, s2 = a * a + b * b;
    #pragma unroll
    for (int o = 16; o; o >>= 1) {
        s  += __shfl_xor_sync(0xffffffffu, s, o);
        s2 += __shfl_xor_sync(0xffffffffu, s2, o);
    }
    float m = s * (1.0f / 64.0f);
    float v = s2 * (1.0f / 64.0f) - m * m;
    float r = rsqrtf(v + 1e-5f);
    size_t base = (size_t)row * 64;
    g_xn[base + lane]      = (a - m) * r * g1[lane]      + be1[lane];
    g_xn[base + lane + 32] = (b - m) * r * g1[lane + 32] + be1[lane + 32];
}

// =========================================================================
// Kernel 2: top-16 nearest neighbors per t (matches jax.lax.top_k order)
// =========================================================================
__global__ void k_topk(const float* __restrict__ c1,
                       const float* __restrict__ c2)
{
    __shared__ unsigned long long res[4][16];
    int warp = threadIdx.x >> 5, lane = threadIdx.x & 31;
    int t = blockIdx.x * 4 + warp;
    float c1t = c1[t], c2t = c2[t];

    unsigned long long best[16];
    #pragma unroll
    for (int i = 0; i < 16; i++) best[i] = 0xFFFFFFFFFFFFFFFFull;

    for (int s = lane; s < T_; s += 32) {
        float d1 = __fadd_rn(c1[s], -c1t);
        float d2 = __fadd_rn(c2[s], -c2t);
        float dist = __fadd_rn(__fmul_rn(d1, d1), __fmul_rn(d2, d2));
        unsigned long long key =
            ((unsigned long long)__float_as_uint(dist) << 32) | (unsigned)s;
        if (key < best[15]) {
            int p = 15;
            while (p > 0 && key < best[p - 1]) { best[p] = best[p - 1]; p--; }
            best[p] = key;
        }
    }
    int p = 0;
    for (int r = 0; r < 16; r++) {
        unsigned long long cand = (p < 16) ? best[p] : 0xFFFFFFFFFFFFFFFFull;
        unsigned long long m = cand;
        #pragma unroll
        for (int o = 16; o; o >>= 1) {
            unsigned long long other = __shfl_xor_sync(0xffffffffu, m, o);
            if (other < m) m = other;
        }
        if (cand == m) p++;
        if (lane == 0) res[warp][r] = m;
    }
    __syncwarp();
    if (lane < 16) {
        unsigned long long key = res[warp][lane];
        int s = (int)(key & 0xFFFFFFFFu);
        g_idx[t * 16 + lane] = s;
        g_c1[t * 16 + lane] = __fadd_rn(c1[s], -c1t);
        g_c2[t * 16 + lane] = __fadd_rn(c2[s], -c2t);
    }
}

// =========================================================================
// Kernel 3: relative-position bias MLP  -> g_bias[t][h][i][j]
// =========================================================================
__global__ void k_bias(const float* __restrict__ Wp1, const float* __restrict__ bp1,
                       const float* __restrict__ Wp2, const float* __restrict__ bp2)
{
    __shared__ float sW1[64], sB1[32], sW2[128], sB2[4], sc1[16], sc2[16];
    int t = blockIdx.x, tid = threadIdx.x;
    if (tid < 64)  sW1[tid] = Wp1[tid];
    if (tid < 32)  sB1[tid] = bp1[tid];
    if (tid < 128) sW2[tid] = Wp2[tid];
    if (tid < 4)   sB2[tid] = bp2[tid];
    if (tid < 16) { sc1[tid] = g_c1[t * 16 + tid]; sc2[tid] = g_c2[t * 16 + tid]; }
    __syncthreads();

    int i = tid >> 4, j = tid & 15;
    float p0 = sc1[i] - sc1[j];
    float p1 = sc2[i] - sc2[j];
    float o0 = sB2[0], o1 = sB2[1], o2 = sB2[2], o3 = sB2[3];
    #pragma unroll
    for (int k = 0; k < 32; k++) {
        float h = fmaf(p0, sW1[k], fmaf(p1, sW1[32 + k], sB1[k]));
        h = (h >= 0.0f) ? h : 0.2f * h;
        o0 = fmaf(h, sW2[k * 4 + 0], o0);
        o1 = fmaf(h, sW2[k * 4 + 1], o1);
        o2 = fmaf(h, sW2[k * 4 + 2], o2);
        o3 = fmaf(h, sW2[k * 4 + 3], o3);
    }
    int base = ((t * 4) * 16 + i) * 16 + j;
    g_bias[base]       = o0;
    g_bias[base + 256] = o1;
    g_bias[base + 512] = o2;
    g_bias[base + 768] = o3;
}

// =========================================================================
// Kernel 4: fused per-(b,t) block (persistent, 2 CTAs/SM)
// =========================================================================
#define OFF_WQ   0
#define OFF_WK   4096
#define OFF_WV   8192
#define OFF_WO   12288
#define OFF_BQ   16384
#define OFF_BK   16448
#define OFF_BV   16512
#define OFF_BO   16576
#define OFF_BN1  16640
#define OFF_WN2  16896
#define OFF_G2   17152
#define OFF_BE2  17216
#define OFF_G3   17280
#define OFF_BE3  18304
#define OFF_SC   19328
#define OFF_BN2  19332
#define OFF_X    19336
#define OFF_Q    20424
#define OFF_K    21512
#define OFF_V    22600
#define OFF_AV   23688
#define OFF_Z    24776
#define OFF_QIN  25864
#define OFF_KIN  25928
#define OFF_RED  25992
#define OFF_R    26120
#define OFF_RS   26136
#define OFF_IDX  26156
#define SMEM_ATTN_FLOATS 26176
#define SMEM_ATTN_BYTES  (SMEM_ATTN_FLOATS * 4)
#define XS 68   // padded row stride for 16x64 tiles (68*4 = 272B, 16B-aligned)

__global__ void __launch_bounds__(256, 2) k_attn(
    const float* __restrict__ Wq, const float* __restrict__ bq,
    const float* __restrict__ Wk, const float* __restrict__ bk,
    const float* __restrict__ Wv, const float* __restrict__ bv,
    const float* __restrict__ logit_scale,
    const float* __restrict__ Wo, const float* __restrict__ bo,
    const float* __restrict__ g2, const float* __restrict__ be2,
    const float* __restrict__ Wn1, const float* __restrict__ bn1,
    const float* __restrict__ Wn2, const float* __restrict__ bn2,
    const float* __restrict__ g3, const float* __restrict__ be3)
{
    extern __shared__ float sm[];
    int tid  = threadIdx.x;
    int wid  = tid >> 5;
    int lane = tid & 31;

    // ---- one-time weight staging ----
    for (int i = tid; i < 4096; i += 256) {
        sm[OFF_WQ + i] = Wq[i];
        sm[OFF_WK + i] = Wk[i];
        sm[OFF_WV + i] = Wv[i];
        sm[OFF_WO + i] = Wo[i];
    }
    if (tid < 64) {
        sm[OFF_BQ + tid] = bq[tid];  sm[OFF_BK + tid] = bk[tid];
        sm[OFF_BV + tid] = bv[tid];  sm[OFF_BO + tid] = bo[tid];
        sm[OFF_G2 + tid] = g2[tid];  sm[OFF_BE2 + tid] = be2[tid];
    }
    sm[OFF_BN1 + tid] = bn1[tid];
    sm[OFF_WN2 + tid] = Wn2[tid];
    for (int i = tid; i < 1024; i += 256) {
        sm[OFF_G3 + i]  = g3[i];
        sm[OFF_BE3 + i] = be3[i];
    }
    if (tid < 4)  sm[OFF_SC + tid] = expf(fminf(logit_scale[tid], logf(100.0f)));
    if (tid == 0) sm[OFF_BN2] = bn2[0];
    __syncthreads();

    int n16 = tid >> 4;          // row 0..15
    int dq  = tid & 15;          // float4 column group
    int* sIdxS = (int*)(sm + OFF_IDX);

    const ulonglong2* wq2 = (const ulonglong2*)(sm + OFF_WQ);
    const ulonglong2* wk2 = (const ulonglong2*)(sm + OFF_WK);
    const ulonglong2* wv2 = (const ulonglong2*)(sm + OFF_WV);
    const ulonglong2* wo2 = (const ulonglong2*)(sm + OFF_WO);

    for (int tile = blockIdx.x; tile < BT_; tile += gridDim.x) {
        int t = tile & (T_ - 1);
        int b = tile >> 12;

        if (tid < 16) sIdxS[tid] = g_idx[t * 16 + tid];
        __syncthreads();

        // gather xg
        for (int i = tid; i < 1024; i += 256) {
            int n = i >> 6, e = i & 63;
            sm[OFF_X + n * XS + e] =
                g_xn[(size_t)(b * T_ + sIdxS[n]) * 64 + e];
        }
        __syncthreads();

        // ---- QKV (FFMA2) ----
        {
            float4 b4;
            b4 = ((const float4*)(sm + OFF_BQ))[dq];
            unsigned long long aq01 = pk2(b4.x, b4.y), aq23 = pk2(b4.z, b4.w);
            b4 = ((const float4*)(sm + OFF_BK))[dq];
            unsigned long long ak01 = pk2(b4.x, b4.y), ak23 = pk2(b4.z, b4.w);
            b4 = ((const float4*)(sm + OFF_BV))[dq];
            unsigned long long av01 = pk2(b4.x, b4.y), av23 = pk2(b4.z, b4.w);
            const float4* xr4 = (const float4*)(sm + OFF_X + n16 * XS);
            #pragma unroll
            for (int e4 = 0; e4 < 16; e4++) {
                float4 x4 = xr4[e4];
                #pragma unroll
                for (int u = 0; u < 4; u++) {
                    float x = (u == 0) ? x4.x : (u == 1) ? x4.y : (u == 2) ? x4.z : x4.w;
                    unsigned long long xx = pk2(x, x);
                    int e = e4 * 4 + u;
                    ulonglong2 w;
                    w = wq2[e * 16 + dq];
                    fma2(aq01, xx, w.x); fma2(aq23, xx, w.y);
                    w = wk2[e * 16 + dq];
                    fma2(ak01, xx, w.x); fma2(ak23, xx, w.y);
                    w = wv2[e * 16 + dq];
                    fma2(av01, xx, w.x); fma2(av23, xx, w.y);
                }
            }
            ((ulonglong2*)(sm + OFF_Q + n16 * XS))[dq] = make_ulonglong2(aq01, aq23);
            ((ulonglong2*)(sm + OFF_K + n16 * XS))[dq] = make_ulonglong2(ak01, ak23);
            ((ulonglong2*)(sm + OFF_V + n16 * XS))[dq] = make_ulonglong2(av01, av23);
        }
        __syncthreads();

        // ---- q/k inverse norms ----
        if (tid < 64) {
            int n = tid & 15, h = tid >> 4;
            const float* q = sm + OFF_Q + n * XS + h * 16;
            const float* k = sm + OFF_K + n * XS + h * 16;
            float sq = 0.0f, sk = 0.0f;
            #pragma unroll
            for (int d = 0; d < 16; d++) { sq = fmaf(q[d], q[d], sq); sk = fmaf(k[d], k[d], sk); }
            sm[OFF_QIN + h * 16 + n] = 1.0f / fmaxf(sqrtf(sq), 1e-6f);
            sm[OFF_KIN + h * 16 + n] = 1.0f / fmaxf(sqrtf(sk), 1e-6f);
        }
        __syncthreads();

        // ---- attention (64 threads: one (h,i) row each) ----
        if (tid < 64) {
            int h = tid >> 4, i = tid & 15, hb = h * 16;
            float qr[16];
            const float* qp = sm + OFF_Q + i * XS + hb;
            #pragma unroll
            for (int d = 0; d < 16; d++) qr[d] = qp[d];
            float qs = sm[OFF_QIN + hb + i] * sm[OFF_SC + h];
            const float* bias_p = g_bias + (((size_t)t * 4 + h) * 16 + i) * 16;

            float sv[16], mx = -1e30f;
            #pragma unroll
            for (int j = 0; j < 16; j++) {
                const float* kp = sm + OFF_K + j * XS + hb;
                float s = 0.0f;
                #pragma unroll
                for (int d = 0; d < 16; d++) s = fmaf(qr[d], kp[d], s);
                s = s * qs * sm[OFF_KIN + hb + j] + bias_p[j];
                sv[j] = s;
                mx = fmaxf(mx, s);
            }
            float den = 0.0f;
            #pragma unroll
            for (int j = 0; j < 16; j++) { sv[j] = expf(sv[j] - mx); den += sv[j]; }
            float inv = 1.0f / den;
            #pragma unroll
            for (int d = 0; d < 16; d++) {
                float acc = 0.0f;
                #pragma unroll
                for (int j = 0; j < 16; j++)
                    acc = fmaf(sv[j], sm[OFF_V + j * XS + hb + d], acc);
                sm[OFF_AV + i * XS + hb + d] = acc * inv;
            }
        }
        __syncthreads();

        // ---- Wo projection + residual (FFMA2) ----
        {
            float4 b4 = ((const float4*)(sm + OFF_BO))[dq];
            unsigned long long a01 = pk2(b4.x, b4.y), a23 = pk2(b4.z, b4.w);
            const float* ar = sm + OFF_AV + n16 * XS;
            #pragma unroll
            for (int e = 0; e < 64; e++) {
                unsigned long long aa = pk2(ar[e], ar[e]);
                ulonglong2 w = wo2[e * 16 + dq];
                fma2(a01, aa, w.x); fma2(a23, aa, w.y);
            }
            ulonglong2 xv = ((const ulonglong2*)(sm + OFF_X + n16 * XS))[dq];
            add2(a01, xv.x); add2(a23, xv.y);
            ((ulonglong2*)(sm + OFF_Q + n16 * XS))[dq] = make_ulonglong2(a01, a23);   // Y
        }
        __syncthreads();

        // ---- LN2 (warp w handles rows 2w, 2w+1) ----
        {
            #pragma unroll
            for (int rr = 0; rr < 2; rr++) {
                int r = wid * 2 + rr;
                const float* yr = sm + OFF_Q + r * XS;
                float a = yr[lane], bb = yr[lane + 32];
                float s = a + bb, s2 = a * a + bb * bb;
                #pragma unroll
                for (int o = 16; o; o >>= 1) {
                    s  += __shfl_xor_sync(0xffffffffu, s, o);
                    s2 += __shfl_xor_sync(0xffffffffu, s2, o);
                }
                float m = s * (1.0f / 64.0f);
                float v = s2 * (1.0f / 64.0f) - m * m;
                float rs = rsqrtf(v + 1e-5f);
                sm[OFF_Z + r * XS + lane] =
                    (a - m) * rs * sm[OFF_G2 + lane] + sm[OFF_BE2 + lane];
                sm[OFF_Z + r * XS + lane + 32] =
                    (bb - m) * rs * sm[OFF_G2 + lane + 32] + sm[OFF_BE2 + lane + 32];
            }
        }
        __syncthreads();

        // ---- FF: thread owns FF unit tid; Wn1 streamed from global (L2),
        //      16 row-accumulators in FFMA2 ----
        {
            unsigned long long acc2[16];
            float bn1v = sm[OFF_BN1 + tid];
            #pragma unroll
            for (int n = 0; n < 16; n++) acc2[n] = pk2(bn1v, 0.0f);

            for (int d4 = 0; d4 < 16; d4++) {
                float w0 = __ldg(&Wn1[(d4 * 4 + 0) * 256 + tid]);
                float w1 = __ldg(&Wn1[(d4 * 4 + 1) * 256 + tid]);
                float w2 = __ldg(&Wn1[(d4 * 4 + 2) * 256 + tid]);
                float w3 = __ldg(&Wn1[(d4 * 4 + 3) * 256 + tid]);
                unsigned long long w01 = pk2(w0, w1), w23 = pk2(w2, w3);
                #pragma unroll
                for (int n = 0; n < 16; n++) {
                    ulonglong2 z = ((const ulonglong2*)(sm + OFF_Z + n * XS))[d4];
                    fma2(acc2[n], z.x, w01);
                    fma2(acc2[n], z.y, w23);
                }
            }
            float wn2v = sm[OFF_WN2 + tid];
            #pragma unroll
            for (int n = 0; n < 16; n++) {
                float2 f2 = upk(acc2[n]);
                float acc = f2.x + f2.y;
                acc = (acc >= 0.0f) ? acc : 0.2f * acc;
                float contrib = acc * wn2v;
                #pragma unroll
                for (int o = 16; o; o >>= 1)
                    contrib += __shfl_xor_sync(0xffffffffu, contrib, o);
                if (lane == 0) sm[OFF_RED + n * 8 + wid] = contrib;
            }
            __syncthreads();
            if (tid < 16) {
                float s = sm[OFF_BN2];
                #pragma unroll
                for (int w2 = 0; w2 < 8; w2++) s += sm[OFF_RED + tid * 8 + w2];
                sm[OFF_R + tid] = (s >= 0.0f) ? s : 0.2f * s;
            }
        }
        __syncthreads();

        // ---- residual add + LN3 over full 1024 + write xu ----
        {
            float lsum = 0.0f, lss = 0.0f;
            for (int i = tid; i < 1024; i += 256) {
                int n = i >> 6, d = i & 63;
                float v = sm[OFF_Z + n * XS + d] + sm[OFF_R + n];
                sm[OFF_X + n * XS + d] = v;
                lsum += v; lss = fmaf(v, v, lss);
            }
            #pragma unroll
            for (int o = 16; o; o >>= 1) {
                lsum += __shfl_xor_sync(0xffffffffu, lsum, o);
                lss  += __shfl_xor_sync(0xffffffffu, lss, o);
            }
            if (lane == 0) { sm[OFF_RS + wid] = lsum; sm[OFF_RS + 8 + wid] = lss; }
            __syncthreads();
            if (tid == 0) {
                float S = 0.0f, S2 = 0.0f;
                #pragma unroll
                for (int w2 = 0; w2 < 8; w2++) { S += sm[OFF_RS + w2]; S2 += sm[OFF_RS + 8 + w2]; }
                float m = S * (1.0f / 1024.0f);
                float v = S2 * (1.0f / 1024.0f) - m * m;
                sm[OFF_RS + 16] = m;
                sm[OFF_RS + 17] = rsqrtf(v + 1e-5f);
            }
            __syncthreads();
            float m = sm[OFF_RS + 16], rs = sm[OFF_RS + 17];
            for (int i = tid; i < 1024; i += 256) {
                int n = i >> 6, d = i & 63;
                g_xu[(size_t)tile * 1024 + i] =
                    (sm[OFF_X + n * XS + d] - m) * rs * sm[OFF_G3 + i] + sm[OFF_BE3 + i];
            }
        }
        __syncthreads();
    }
}

// =========================================================================
// Kernel 5: fused head: out = lrelu(lrelu(xu@Wu1+bu1)@Wu2+bu2)
// 64-row x 128-col block tile, 4x8 microtile, FFMA2, transposed sA
// =========================================================================
__global__ void __launch_bounds__(256) k_head(
    const float* __restrict__ Wu1, const float* __restrict__ bu1,
    const float* __restrict__ Wu2, const float* __restrict__ bu2,
    float* __restrict__ out)
{
    __shared__ float sA[32][68];     // [k][row] transposed
    __shared__ float sB[32][132];    // [k][j]
    __shared__ float sRed[64][17];

    int tid = threadIdx.x;
    int tx = tid & 15, ty = tid >> 4;   // tx: 8-col group, ty: 4-row group
    int r0 = blockIdx.x * 64;

    float t_out[4] = {0.0f, 0.0f, 0.0f, 0.0f};

    for (int jt = 0; jt < 8; jt++) {
        int j0 = jt * 128;
        unsigned long long acc[4][4];   // [row][colpair]
        #pragma unroll
        for (int i = 0; i < 4; i++)
            #pragma unroll
            for (int c = 0; c < 4; c++) acc[i][c] = 0ull;

        for (int k0 = 0; k0 < 1024; k0 += 32) {
            // stage A transposed: 64 rows x 32 k
            #pragma unroll
            for (int v = 0; v < 2; v++) {
                int i = tid + v * 256;            // 0..511 float4s
                int r = i >> 3, k4 = i & 7;
                float4 a4 = *(const float4*)&g_xu[(size_t)(r0 + r) * 1024 + k0 + k4 * 4];
                sA[k4 * 4 + 0][r] = a4.x; sA[k4 * 4 + 1][r] = a4.y;
                sA[k4 * 4 + 2][r] = a4.z; sA[k4 * 4 + 3][r] = a4.w;
            }
            // stage B: 32 k x 128 j
            #pragma unroll
            for (int v = 0; v < 4; v++) {
                int i = tid + v * 256;            // 0..1023 float4s
                int k = i >> 5, j4 = i & 31;
                *(float4*)&sB[k][j4 * 4] =
                    *(const float4*)&Wu1[(size_t)(k0 + k) * 1024 + j0 + j4 * 4];
            }
            __syncthreads();
            #pragma unroll
            for (int k = 0; k < 32; k++) {
                float4 a4 = *(const float4*)&sA[k][ty * 4];
                ulonglong2 b0 = *(const ulonglong2*)&sB[k][tx * 8];
                ulonglong2 b1 = *(const ulonglong2*)&sB[k][tx * 8 + 4];
                unsigned long long aa;
                aa = pk2(a4.x, a4.x);
                fma2(acc[0][0], aa, b0.x); fma2(acc[0][1], aa, b0.y);
                fma2(acc[0][2], aa, b1.x); fma2(acc[0][3], aa, b1.y);
                aa = pk2(a4.y, a4.y);
                fma2(acc[1][0], aa, b0.x); fma2(acc[1][1], aa, b0.y);
                fma2(acc[1][2], aa, b1.x); fma2(acc[1][3], aa, b1.y);
                aa = pk2(a4.z, a4.z);
                fma2(acc[2][0], aa, b0.x); fma2(acc[2][1], aa, b0.y);
                fma2(acc[2][2], aa, b1.x); fma2(acc[2][3], aa, b1.y);
                aa = pk2(a4.w, a4.w);
                fma2(acc[3][0], aa, b0.x); fma2(acc[3][1], aa, b0.y);
                fma2(acc[3][2], aa, b1.x); fma2(acc[3][3], aa, b1.y);
            }
            __syncthreads();
        }
        // fused lrelu + Wu2 partial reduction for this j-tile
        #pragma unroll
        for (int c = 0; c < 4; c++) {
            int j = j0 + tx * 8 + c * 2;
            float bj0 = __ldg(&bu1[j]),     wj0 = __ldg(&Wu2[j]);
            float bj1 = __ldg(&bu1[j + 1]), wj1 = __ldg(&Wu2[j + 1]);
            #pragma unroll
            for (int i = 0; i < 4; i++) {
                float2 h2 = upk(acc[i][c]);
                float h0 = h2.x + bj0; h0 = (h0 >= 0.0f) ? h0 : 0.2f * h0;
                float h1 = h2.y + bj1; h1 = (h1 >= 0.0f) ? h1 : 0.2f * h1;
                t_out[i] = fmaf(wj0, h0, fmaf(wj1, h1, t_out[i]));
            }
        }
    }
    #pragma unroll
    for (int i = 0; i < 4; i++) sRed[ty * 4 + i][tx] = t_out[i];
    __syncthreads();
    if (tid < 64) {
        float s = 0.0f;
        #pragma unroll
        for (int x = 0; x < 16; x++) s += sRed[tid][x];
        s += __ldg(&bu2[0]);
        out[r0 + tid] = (s >= 0.0f) ? s : 0.2f * s;
    }
}

// =========================================================================
// launch
// =========================================================================
extern "C" void kernel_launch(void* const* d_in, const int* in_sizes, int n_in,
                              void* d_out, int out_size)
{
    const float* x       = (const float*)d_in[0];
    const float* coords1 = (const float*)d_in[1];
    const float* coords2 = (const float*)d_in[2];
    const float* g1      = (const float*)d_in[3];
    const float* be1     = (const float*)d_in[4];
    const float* Wq      = (const float*)d_in[5];
    const float* bq      = (const float*)d_in[6];
    const float* Wk      = (const float*)d_in[7];
    const float* bk      = (const float*)d_in[8];
    const float* Wv      = (const float*)d_in[9];
    const float* bv      = (const float*)d_in[10];
    const float* ls      = (const float*)d_in[11];
    const float* Wo      = (const float*)d_in[12];
    const float* bo      = (const float*)d_in[13];
    const float* Wp1     = (const float*)d_in[14];
    const float* bp1     = (const float*)d_in[15];
    const float* Wp2     = (const float*)d_in[16];
    const float* bp2     = (const float*)d_in[17];
    const float* g2      = (const float*)d_in[18];
    const float* be2     = (const float*)d_in[19];
    const float* Wn1     = (const float*)d_in[20];
    const float* bn1     = (const float*)d_in[21];
    const float* Wn2     = (const float*)d_in[22];
    const float* bn2     = (const float*)d_in[23];
    const float* g3      = (const float*)d_in[24];
    const float* be3     = (const float*)d_in[25];
    const float* Wu1     = (const float*)d_in[26];
    const float* bu1     = (const float*)d_in[27];
    const float* Wu2     = (const float*)d_in[28];
    const float* bu2     = (const float*)d_in[29];
    float* out = (float*)d_out;

    cudaFuncSetAttribute(k_attn, cudaFuncAttributeMaxDynamicSharedMemorySize,
                         SMEM_ATTN_BYTES);

    k_ln1 <<<BT_ / 8, 256>>>(x, g1, be1);
    k_topk<<<T_ / 4, 128>>>(coords1, coords2);
    k_bias<<<T_, 256>>>(Wp1, bp1, Wp2, bp2);
    k_attn<<<296, 256, SMEM_ATTN_BYTES>>>(Wq, bq, Wk, bk, Wv, bv, ls, Wo, bo,
                                          g2, be2, Wn1, bn1, Wn2, bn2, g3, be3);
    k_head<<<BT_ / 64, 256>>>(Wu1, bu1, Wu2, bu2, out);
}

// round 9
// speedup vs baseline: 1.6998x; 1.6998x over previous
#include <cuda_runtime.h>
#include <cuda_bf16.h>
#include <math.h>
#include <stdint.h>

// Problem constants
#define B_   8
#define T_   4096
#define NH_  16
#define MD_  64
#define FF_  256
#define HEADS_ 4
#define DH_  16
#define PEH_ 32
#define BT_  (B_ * T_)        // 32768

// ---------------- packed f32x2 helpers (k_attn) ----------------
__device__ __forceinline__ unsigned long long pk2(float x, float y) {
    unsigned long long r;
    asm("mov.b64 %0, {%1, %2};" : "=l"(r) : "f"(x), "f"(y));
    return r;
}
__device__ __forceinline__ void fma2(unsigned long long& d,
                                     unsigned long long a, unsigned long long b) {
    asm("fma.rn.f32x2 %0, %1, %2, %0;" : "+l"(d) : "l"(a), "l"(b));
}
__device__ __forceinline__ void add2(unsigned long long& d, unsigned long long a) {
    asm("add.rn.f32x2 %0, %0, %1;" : "+l"(d) : "l"(a));
}
__device__ __forceinline__ float2 upk(unsigned long long v) {
    float lo, hi;
    asm("mov.b64 {%0, %1}, %2;" : "=f"(lo), "=f"(hi) : "l"(v));
    return make_float2(lo, hi);
}

// ---------------- mma.sync helpers (base ISA, works on sm_103) ----------
__device__ __forceinline__ uint32_t smem_u32(const void* p) {
    uint32_t a;
    asm("{ .reg .u64 t; cvta.to.shared.u64 t, %1; cvt.u32.u64 %0, t; }"
        : "=r"(a) : "l"(p));
    return a;
}
__device__ __forceinline__ void ldm_x4(uint32_t* r, uint32_t addr) {
    asm volatile("ldmatrix.sync.aligned.m8n8.x4.shared.b16 {%0,%1,%2,%3}, [%4];"
                 : "=r"(r[0]), "=r"(r[1]), "=r"(r[2]), "=r"(r[3]) : "r"(addr));
}
__device__ __forceinline__ void mma_bf16(float* c, const uint32_t* a,
                                         const uint32_t* b) {
    asm volatile(
        "mma.sync.aligned.m16n8k16.row.col.f32.bf16.bf16.f32 "
        "{%0,%1,%2,%3}, {%4,%5,%6,%7}, {%8,%9}, {%0,%1,%2,%3};"
        : "+f"(c[0]), "+f"(c[1]), "+f"(c[2]), "+f"(c[3])
        : "r"(a[0]), "r"(a[1]), "r"(a[2]), "r"(a[3]), "r"(b[0]), "r"(b[1]));
}

// ---------------- device scratch (static, no allocations) ----------------
__device__ float g_xn[(size_t)BT_ * MD_];            // LN1 output       8 MB
__device__ int   g_idx[T_ * NH_];
__device__ float g_c1[T_ * NH_];
__device__ float g_c2[T_ * NH_];
__device__ float g_bias[(size_t)T_ * HEADS_ * NH_ * NH_];   // 16 MB
__device__ __nv_bfloat16 g_xu_hi[(size_t)BT_ * 1024];       // 64 MB
__device__ __nv_bfloat16 g_xu_lo[(size_t)BT_ * 1024];       // 64 MB
__device__ __nv_bfloat16 g_w1t_hi[1024 * 1024];             // Wu1^T hi  2 MB
__device__ __nv_bfloat16 g_w1t_lo[1024 * 1024];             // Wu1^T lo  2 MB

// =========================================================================
// Kernel 1: LayerNorm over x rows (B*T rows of 64)
// =========================================================================
__global__ void k_ln1(const float* __restrict__ x,
                      const float* __restrict__ g1,
                      const float* __restrict__ be1)
{
    int row  = blockIdx.x * 8 + (threadIdx.x >> 5);
    int lane = threadIdx.x & 31;
    const float* xr = x + (size_t)row * 64;
    float a = xr[lane], b = xr[lane + 32];
    float s = a + b, s2 = a * a + b * b;
    #pragma unroll
    for (int o = 16; o; o >>= 1) {
        s  += __shfl_xor_sync(0xffffffffu, s, o);
        s2 += __shfl_xor_sync(0xffffffffu, s2, o);
    }
    float m = s * (1.0f / 64.0f);
    float v = s2 * (1.0f / 64.0f) - m * m;
    float r = rsqrtf(v + 1e-5f);
    size_t base = (size_t)row * 64;
    g_xn[base + lane]      = (a - m) * r * g1[lane]      + be1[lane];
    g_xn[base + lane + 32] = (b - m) * r * g1[lane + 32] + be1[lane + 32];
}

// =========================================================================
// Kernel 2: top-16 nearest neighbors per t (matches jax.lax.top_k order)
// =========================================================================
__global__ void k_topk(const float* __restrict__ c1,
                       const float* __restrict__ c2)
{
    __shared__ unsigned long long res[4][16];
    int warp = threadIdx.x >> 5, lane = threadIdx.x & 31;
    int t = blockIdx.x * 4 + warp;
    float c1t = c1[t], c2t = c2[t];

    unsigned long long best[16];
    #pragma unroll
    for (int i = 0; i < 16; i++) best[i] = 0xFFFFFFFFFFFFFFFFull;

    for (int s = lane; s < T_; s += 32) {
        float d1 = __fadd_rn(c1[s], -c1t);
        float d2 = __fadd_rn(c2[s], -c2t);
        float dist = __fadd_rn(__fmul_rn(d1, d1), __fmul_rn(d2, d2));
        unsigned long long key =
            ((unsigned long long)__float_as_uint(dist) << 32) | (unsigned)s;
        if (key < best[15]) {
            int p = 15;
            while (p > 0 && key < best[p - 1]) { best[p] = best[p - 1]; p--; }
            best[p] = key;
        }
    }
    int p = 0;
    for (int r = 0; r < 16; r++) {
        unsigned long long cand = (p < 16) ? best[p] : 0xFFFFFFFFFFFFFFFFull;
        unsigned long long m = cand;
        #pragma unroll
        for (int o = 16; o; o >>= 1) {
            unsigned long long other = __shfl_xor_sync(0xffffffffu, m, o);
            if (other < m) m = other;
        }
        if (cand == m) p++;
        if (lane == 0) res[warp][r] = m;
    }
    __syncwarp();
    if (lane < 16) {
        unsigned long long key = res[warp][lane];
        int s = (int)(key & 0xFFFFFFFFu);
        g_idx[t * 16 + lane] = s;
        g_c1[t * 16 + lane] = __fadd_rn(c1[s], -c1t);
        g_c2[t * 16 + lane] = __fadd_rn(c2[s], -c2t);
    }
}

// =========================================================================
// Kernel 3: relative-position bias MLP  -> g_bias[t][h][i][j]
// =========================================================================
__global__ void k_bias(const float* __restrict__ Wp1, const float* __restrict__ bp1,
                       const float* __restrict__ Wp2, const float* __restrict__ bp2)
{
    __shared__ float sW1[64], sB1[32], sW2[128], sB2[4], sc1[16], sc2[16];
    int t = blockIdx.x, tid = threadIdx.x;
    if (tid < 64)  sW1[tid] = Wp1[tid];
    if (tid < 32)  sB1[tid] = bp1[tid];
    if (tid < 128) sW2[tid] = Wp2[tid];
    if (tid < 4)   sB2[tid] = bp2[tid];
    if (tid < 16) { sc1[tid] = g_c1[t * 16 + tid]; sc2[tid] = g_c2[t * 16 + tid]; }
    __syncthreads();

    int i = tid >> 4, j = tid & 15;
    float p0 = sc1[i] - sc1[j];
    float p1 = sc2[i] - sc2[j];
    float o0 = sB2[0], o1 = sB2[1], o2 = sB2[2], o3 = sB2[3];
    #pragma unroll
    for (int k = 0; k < 32; k++) {
        float h = fmaf(p0, sW1[k], fmaf(p1, sW1[32 + k], sB1[k]));
        h = (h >= 0.0f) ? h : 0.2f * h;
        o0 = fmaf(h, sW2[k * 4 + 0], o0);
        o1 = fmaf(h, sW2[k * 4 + 1], o1);
        o2 = fmaf(h, sW2[k * 4 + 2], o2);
        o3 = fmaf(h, sW2[k * 4 + 3], o3);
    }
    int base = ((t * 4) * 16 + i) * 16 + j;
    g_bias[base]       = o0;
    g_bias[base + 256] = o1;
    g_bias[base + 512] = o2;
    g_bias[base + 768] = o3;
}

// =========================================================================
// Kernel 3b: transpose + bf16-split Wu1 -> g_w1t_hi/lo  [j][k]
// =========================================================================
__global__ void k_split(const float* __restrict__ Wu1)
{
    __shared__ float tbuf[32][33];
    int bx = blockIdx.x, by = blockIdx.y;
    int tx = threadIdx.x & 31, ty = threadIdx.x >> 5;   // ty 0..7
    #pragma unroll
    for (int i = 0; i < 4; i++) {
        int r = by * 32 + ty + i * 8;                   // k
        tbuf[ty + i * 8][tx] = Wu1[(size_t)r * 1024 + bx * 32 + tx];
    }
    __syncthreads();
    #pragma unroll
    for (int i = 0; i < 4; i++) {
        int j = bx * 32 + ty + i * 8;                   // output row (j)
        int k = by * 32 + tx;                           // output col (k)
        float v = tbuf[tx][ty + i * 8];
        __nv_bfloat16 hi = __float2bfloat16(v);
        g_w1t_hi[(size_t)j * 1024 + k] = hi;
        g_w1t_lo[(size_t)j * 1024 + k] = __float2bfloat16(v - __bfloat162float(hi));
    }
}

// =========================================================================
// Kernel 4: fused per-(b,t) block (persistent, 2 CTAs/SM)
// epilogue writes bf16 hi/lo split of xu
// =========================================================================
#define OFF_WQ   0
#define OFF_WK   4096
#define OFF_WV   8192
#define OFF_WO   12288
#define OFF_BQ   16384
#define OFF_BK   16448
#define OFF_BV   16512
#define OFF_BO   16576
#define OFF_BN1  16640
#define OFF_WN2  16896
#define OFF_G2   17152
#define OFF_BE2  17216
#define OFF_G3   17280
#define OFF_BE3  18304
#define OFF_SC   19328
#define OFF_BN2  19332
#define OFF_X    19336
#define OFF_Q    20424
#define OFF_K    21512
#define OFF_V    22600
#define OFF_AV   23688
#define OFF_Z    24776
#define OFF_QIN  25864
#define OFF_KIN  25928
#define OFF_RED  25992
#define OFF_R    26120
#define OFF_RS   26136
#define OFF_IDX  26156
#define SMEM_ATTN_FLOATS 26176
#define SMEM_ATTN_BYTES  (SMEM_ATTN_FLOATS * 4)
#define XS 68

__global__ void __launch_bounds__(256, 2) k_attn(
    const float* __restrict__ Wq, const float* __restrict__ bq,
    const float* __restrict__ Wk, const float* __restrict__ bk,
    const float* __restrict__ Wv, const float* __restrict__ bv,
    const float* __restrict__ logit_scale,
    const float* __restrict__ Wo, const float* __restrict__ bo,
    const float* __restrict__ g2, const float* __restrict__ be2,
    const float* __restrict__ Wn1, const float* __restrict__ bn1,
    const float* __restrict__ Wn2, const float* __restrict__ bn2,
    const float* __restrict__ g3, const float* __restrict__ be3)
{
    extern __shared__ float sm[];
    int tid  = threadIdx.x;
    int wid  = tid >> 5;
    int lane = tid & 31;

    for (int i = tid; i < 4096; i += 256) {
        sm[OFF_WQ + i] = Wq[i];
        sm[OFF_WK + i] = Wk[i];
        sm[OFF_WV + i] = Wv[i];
        sm[OFF_WO + i] = Wo[i];
    }
    if (tid < 64) {
        sm[OFF_BQ + tid] = bq[tid];  sm[OFF_BK + tid] = bk[tid];
        sm[OFF_BV + tid] = bv[tid];  sm[OFF_BO + tid] = bo[tid];
        sm[OFF_G2 + tid] = g2[tid];  sm[OFF_BE2 + tid] = be2[tid];
    }
    sm[OFF_BN1 + tid] = bn1[tid];
    sm[OFF_WN2 + tid] = Wn2[tid];
    for (int i = tid; i < 1024; i += 256) {
        sm[OFF_G3 + i]  = g3[i];
        sm[OFF_BE3 + i] = be3[i];
    }
    if (tid < 4)  sm[OFF_SC + tid] = expf(fminf(logit_scale[tid], logf(100.0f)));
    if (tid == 0) sm[OFF_BN2] = bn2[0];
    __syncthreads();

    int n16 = tid >> 4;
    int dq  = tid & 15;
    int* sIdxS = (int*)(sm + OFF_IDX);

    const ulonglong2* wq2 = (const ulonglong2*)(sm + OFF_WQ);
    const ulonglong2* wk2 = (const ulonglong2*)(sm + OFF_WK);
    const ulonglong2* wv2 = (const ulonglong2*)(sm + OFF_WV);
    const ulonglong2* wo2 = (const ulonglong2*)(sm + OFF_WO);

    for (int tile = blockIdx.x; tile < BT_; tile += gridDim.x) {
        int t = tile & (T_ - 1);
        int b = tile >> 12;

        if (tid < 16) sIdxS[tid] = g_idx[t * 16 + tid];
        __syncthreads();

        for (int i = tid; i < 1024; i += 256) {
            int n = i >> 6, e = i & 63;
            sm[OFF_X + n * XS + e] =
                g_xn[(size_t)(b * T_ + sIdxS[n]) * 64 + e];
        }
        __syncthreads();

        // ---- QKV ----
        {
            float4 b4;
            b4 = ((const float4*)(sm + OFF_BQ))[dq];
            unsigned long long aq01 = pk2(b4.x, b4.y), aq23 = pk2(b4.z, b4.w);
            b4 = ((const float4*)(sm + OFF_BK))[dq];
            unsigned long long ak01 = pk2(b4.x, b4.y), ak23 = pk2(b4.z, b4.w);
            b4 = ((const float4*)(sm + OFF_BV))[dq];
            unsigned long long av01 = pk2(b4.x, b4.y), av23 = pk2(b4.z, b4.w);
            const float4* xr4 = (const float4*)(sm + OFF_X + n16 * XS);
            #pragma unroll
            for (int e4 = 0; e4 < 16; e4++) {
                float4 x4 = xr4[e4];
                #pragma unroll
                for (int u = 0; u < 4; u++) {
                    float x = (u == 0) ? x4.x : (u == 1) ? x4.y : (u == 2) ? x4.z : x4.w;
                    unsigned long long xx = pk2(x, x);
                    int e = e4 * 4 + u;
                    ulonglong2 w;
                    w = wq2[e * 16 + dq];
                    fma2(aq01, xx, w.x); fma2(aq23, xx, w.y);
                    w = wk2[e * 16 + dq];
                    fma2(ak01, xx, w.x); fma2(ak23, xx, w.y);
                    w = wv2[e * 16 + dq];
                    fma2(av01, xx, w.x); fma2(av23, xx, w.y);
                }
            }
            ((ulonglong2*)(sm + OFF_Q + n16 * XS))[dq] = make_ulonglong2(aq01, aq23);
            ((ulonglong2*)(sm + OFF_K + n16 * XS))[dq] = make_ulonglong2(ak01, ak23);
            ((ulonglong2*)(sm + OFF_V + n16 * XS))[dq] = make_ulonglong2(av01, av23);
        }
        __syncthreads();

        if (tid < 64) {
            int n = tid & 15, h = tid >> 4;
            const float* q = sm + OFF_Q + n * XS + h * 16;
            const float* k = sm + OFF_K + n * XS + h * 16;
            float sq = 0.0f, sk = 0.0f;
            #pragma unroll
            for (int d = 0; d < 16; d++) { sq = fmaf(q[d], q[d], sq); sk = fmaf(k[d], k[d], sk); }
            sm[OFF_QIN + h * 16 + n] = 1.0f / fmaxf(sqrtf(sq), 1e-6f);
            sm[OFF_KIN + h * 16 + n] = 1.0f / fmaxf(sqrtf(sk), 1e-6f);
        }
        __syncthreads();

        if (tid < 64) {
            int h = tid >> 4, i = tid & 15, hb = h * 16;
            float qr[16];
            const float* qp = sm + OFF_Q + i * XS + hb;
            #pragma unroll
            for (int d = 0; d < 16; d++) qr[d] = qp[d];
            float qs = sm[OFF_QIN + hb + i] * sm[OFF_SC + h];
            const float* bias_p = g_bias + (((size_t)t * 4 + h) * 16 + i) * 16;

            float sv[16], mx = -1e30f;
            #pragma unroll
            for (int j = 0; j < 16; j++) {
                const float* kp = sm + OFF_K + j * XS + hb;
                float s = 0.0f;
                #pragma unroll
                for (int d = 0; d < 16; d++) s = fmaf(qr[d], kp[d], s);
                s = s * qs * sm[OFF_KIN + hb + j] + bias_p[j];
                sv[j] = s;
                mx = fmaxf(mx, s);
            }
            float den = 0.0f;
            #pragma unroll
            for (int j = 0; j < 16; j++) { sv[j] = expf(sv[j] - mx); den += sv[j]; }
            float inv = 1.0f / den;
            #pragma unroll
            for (int d = 0; d < 16; d++) {
                float acc = 0.0f;
                #pragma unroll
                for (int j = 0; j < 16; j++)
                    acc = fmaf(sv[j], sm[OFF_V + j * XS + hb + d], acc);
                sm[OFF_AV + i * XS + hb + d] = acc * inv;
            }
        }
        __syncthreads();

        // ---- Wo projection + residual ----
        {
            float4 b4 = ((const float4*)(sm + OFF_BO))[dq];
            unsigned long long a01 = pk2(b4.x, b4.y), a23 = pk2(b4.z, b4.w);
            const float* ar = sm + OFF_AV + n16 * XS;
            #pragma unroll
            for (int e = 0; e < 64; e++) {
                unsigned long long aa = pk2(ar[e], ar[e]);
                ulonglong2 w = wo2[e * 16 + dq];
                fma2(a01, aa, w.x); fma2(a23, aa, w.y);
            }
            ulonglong2 xv = ((const ulonglong2*)(sm + OFF_X + n16 * XS))[dq];
            add2(a01, xv.x); add2(a23, xv.y);
            ((ulonglong2*)(sm + OFF_Q + n16 * XS))[dq] = make_ulonglong2(a01, a23);
        }
        __syncthreads();

        // ---- LN2 ----
        {
            #pragma unroll
            for (int rr = 0; rr < 2; rr++) {
                int r = wid * 2 + rr;
                const float* yr = sm + OFF_Q + r * XS;
                float a = yr[lane], bb = yr[lane + 32];
                float s = a + bb, s2 = a * a + bb * bb;
                #pragma unroll
                for (int o = 16; o; o >>= 1) {
                    s  += __shfl_xor_sync(0xffffffffu, s, o);
                    s2 += __shfl_xor_sync(0xffffffffu, s2, o);
                }
                float m = s * (1.0f / 64.0f);
                float v = s2 * (1.0f / 64.0f) - m * m;
                float rs = rsqrtf(v + 1e-5f);
                sm[OFF_Z + r * XS + lane] =
                    (a - m) * rs * sm[OFF_G2 + lane] + sm[OFF_BE2 + lane];
                sm[OFF_Z + r * XS + lane + 32] =
                    (bb - m) * rs * sm[OFF_G2 + lane + 32] + sm[OFF_BE2 + lane + 32];
            }
        }
        __syncthreads();

        // ---- FF ----
        {
            unsigned long long acc2[16];
            float bn1v = sm[OFF_BN1 + tid];
            #pragma unroll
            for (int n = 0; n < 16; n++) acc2[n] = pk2(bn1v, 0.0f);

            for (int d4 = 0; d4 < 16; d4++) {
                float w0 = __ldg(&Wn1[(d4 * 4 + 0) * 256 + tid]);
                float w1 = __ldg(&Wn1[(d4 * 4 + 1) * 256 + tid]);
                float w2 = __ldg(&Wn1[(d4 * 4 + 2) * 256 + tid]);
                float w3 = __ldg(&Wn1[(d4 * 4 + 3) * 256 + tid]);
                unsigned long long w01 = pk2(w0, w1), w23 = pk2(w2, w3);
                #pragma unroll
                for (int n = 0; n < 16; n++) {
                    ulonglong2 z = ((const ulonglong2*)(sm + OFF_Z + n * XS))[d4];
                    fma2(acc2[n], z.x, w01);
                    fma2(acc2[n], z.y, w23);
                }
            }
            float wn2v = sm[OFF_WN2 + tid];
            #pragma unroll
            for (int n = 0; n < 16; n++) {
                float2 f2 = upk(acc2[n]);
                float acc = f2.x + f2.y;
                acc = (acc >= 0.0f) ? acc : 0.2f * acc;
                float contrib = acc * wn2v;
                #pragma unroll
                for (int o = 16; o; o >>= 1)
                    contrib += __shfl_xor_sync(0xffffffffu, contrib, o);
                if (lane == 0) sm[OFF_RED + n * 8 + wid] = contrib;
            }
            __syncthreads();
            if (tid < 16) {
                float s = sm[OFF_BN2];
                #pragma unroll
                for (int w2 = 0; w2 < 8; w2++) s += sm[OFF_RED + tid * 8 + w2];
                sm[OFF_R + tid] = (s >= 0.0f) ? s : 0.2f * s;
            }
        }
        __syncthreads();

        // ---- residual + LN3 + write bf16-split xu ----
        {
            float lsum = 0.0f, lss = 0.0f;
            for (int i = tid; i < 1024; i += 256) {
                int n = i >> 6, d = i & 63;
                float v = sm[OFF_Z + n * XS + d] + sm[OFF_R + n];
                sm[OFF_X + n * XS + d] = v;
                lsum += v; lss = fmaf(v, v, lss);
            }
            #pragma unroll
            for (int o = 16; o; o >>= 1) {
                lsum += __shfl_xor_sync(0xffffffffu, lsum, o);
                lss  += __shfl_xor_sync(0xffffffffu, lss, o);
            }
            if (lane == 0) { sm[OFF_RS + wid] = lsum; sm[OFF_RS + 8 + wid] = lss; }
            __syncthreads();
            if (tid == 0) {
                float S = 0.0f, S2 = 0.0f;
                #pragma unroll
                for (int w2 = 0; w2 < 8; w2++) { S += sm[OFF_RS + w2]; S2 += sm[OFF_RS + 8 + w2]; }
                float m = S * (1.0f / 1024.0f);
                float v = S2 * (1.0f / 1024.0f) - m * m;
                sm[OFF_RS + 16] = m;
                sm[OFF_RS + 17] = rsqrtf(v + 1e-5f);
            }
            __syncthreads();
            float m = sm[OFF_RS + 16], rs = sm[OFF_RS + 17];
            for (int i = tid; i < 1024; i += 256) {
                int n = i >> 6, d = i & 63;
                float vv = (sm[OFF_X + n * XS + d] - m) * rs * sm[OFF_G3 + i] + sm[OFF_BE3 + i];
                __nv_bfloat16 hi = __float2bfloat16(vv);
                g_xu_hi[(size_t)tile * 1024 + i] = hi;
                g_xu_lo[(size_t)tile * 1024 + i] =
                    __float2bfloat16(vv - __bfloat162float(hi));
            }
        }
        __syncthreads();
    }
}

// =========================================================================
// Kernel 5: mma.sync bf16-split head GEMM + fused lrelu/Wu2 epilogue
// block 128 rows x 128 j-cols, K chunks of 32, warp tile 32x64
// =========================================================================
#define HM_SAH  0        // A hi: 128 rows x 40 bf16 (32 used) = 10240 B
#define HM_SAL  10240
#define HM_SBH  20480
#define HM_SBL  30720
#define HM_BU1  40960    // 1024 f32
#define HM_WU2  45056    // 1024 f32
#define HM_RED  49152    // 128 rows x 2 warp_n x f32
#define HM_SMEM 50176
#define HMS 40           // smem row stride in bf16

__global__ void __launch_bounds__(256) k_head_mma(
    const float* __restrict__ bu1, const float* __restrict__ Wu2,
    const float* __restrict__ bu2, float* __restrict__ out)
{
    extern __shared__ char smc[];
    uint32_t sb = smem_u32(smc);
    int tid = threadIdx.x, wid = tid >> 5, lane = tid & 31;
    int warp_m = wid & 3, warp_n = wid >> 2;

    float* sbu1 = (float*)(smc + HM_BU1);
    float* sWu2 = (float*)(smc + HM_WU2);
    float* sRed = (float*)(smc + HM_RED);
    for (int i = tid; i < 1024; i += 256) { sbu1[i] = bu1[i]; sWu2[i] = Wu2[i]; }

    int r0 = blockIdx.x * 128;
    float orow[4] = {0.0f, 0.0f, 0.0f, 0.0f};

    // ldmatrix lane-address components
    int lm_r = (lane & 7) + ((lane >> 3) & 1) * 8;   // A: row within m16
    int lm_k = (lane >> 4) * 8;                      // A: k-half
    int lb_r = (lane & 7) + ((lane >> 4) & 1) * 8;   // B: j row within 16
    int lb_k = ((lane >> 3) & 1) * 8;                // B: k-half

    for (int jt = 0; jt < 8; jt++) {
        int j0 = jt * 128;
        float acc[2][8][4];
        #pragma unroll
        for (int mi = 0; mi < 2; mi++)
            #pragma unroll
            for (int ni = 0; ni < 8; ni++)
                #pragma unroll
                for (int e = 0; e < 4; e++) acc[mi][ni][e] = 0.0f;

        for (int kc = 0; kc < 32; kc++) {
            int k0 = kc * 32;
            // ---- stage A/B hi+lo (128x32 bf16 each) ----
            #pragma unroll
            for (int v = 0; v < 2; v++) {
                int idx = tid + v * 256;           // 0..511
                int r = idx >> 2, k8 = idx & 3;
                uint32_t so = (uint32_t)(r * (HMS * 2) + k8 * 16);
                size_t ga = (size_t)(r0 + r) * 1024 + k0 + k8 * 8;
                size_t gb = (size_t)(j0 + r) * 1024 + k0 + k8 * 8;
                *(uint4*)(smc + HM_SAH + so) = *(const uint4*)&g_xu_hi[ga];
                *(uint4*)(smc + HM_SAL + so) = *(const uint4*)&g_xu_lo[ga];
                *(uint4*)(smc + HM_SBH + so) = *(const uint4*)&g_w1t_hi[gb];
                *(uint4*)(smc + HM_SBL + so) = *(const uint4*)&g_w1t_lo[gb];
            }
            __syncthreads();

            #pragma unroll
            for (int k16 = 0; k16 < 2; k16++) {
                int ko = k16 * 16;
                uint32_t ah[2][4], bh[8][2];
                // A hi frags
                #pragma unroll
                for (int mi = 0; mi < 2; mi++) {
                    uint32_t addr = sb + HM_SAH +
                        (uint32_t)(((warp_m * 32 + mi * 16 + lm_r) * HMS + ko + lm_k) * 2);
                    ldm_x4(ah[mi], addr);
                }
                // B hi frags (x4 loads 2 n8 frags)
                #pragma unroll
                for (int n2 = 0; n2 < 4; n2++) {
                    uint32_t r4[4];
                    uint32_t addr = sb + HM_SBH +
                        (uint32_t)(((warp_n * 64 + n2 * 16 + lb_r) * HMS + ko + lb_k) * 2);
                    ldm_x4(r4, addr);
                    bh[n2 * 2][0] = r4[0]; bh[n2 * 2][1] = r4[1];
                    bh[n2 * 2 + 1][0] = r4[2]; bh[n2 * 2 + 1][1] = r4[3];
                }
                // hi*hi
                #pragma unroll
                for (int mi = 0; mi < 2; mi++)
                    #pragma unroll
                    for (int ni = 0; ni < 8; ni++)
                        mma_bf16(acc[mi][ni], ah[mi], bh[ni]);
                // lo*hi
                {
                    uint32_t al[2][4];
                    #pragma unroll
                    for (int mi = 0; mi < 2; mi++) {
                        uint32_t addr = sb + HM_SAL +
                            (uint32_t)(((warp_m * 32 + mi * 16 + lm_r) * HMS + ko + lm_k) * 2);
                        ldm_x4(al[mi], addr);
                    }
                    #pragma unroll
                    for (int mi = 0; mi < 2; mi++)
                        #pragma unroll
                        for (int ni = 0; ni < 8; ni++)
                            mma_bf16(acc[mi][ni], al[mi], bh[ni]);
                }
                // hi*lo
                {
                    uint32_t bl[8][2];
                    #pragma unroll
                    for (int n2 = 0; n2 < 4; n2++) {
                        uint32_t r4[4];
                        uint32_t addr = sb + HM_SBL +
                            (uint32_t)(((warp_n * 64 + n2 * 16 + lb_r) * HMS + ko + lb_k) * 2);
                        ldm_x4(r4, addr);
                        bl[n2 * 2][0] = r4[0]; bl[n2 * 2][1] = r4[1];
                        bl[n2 * 2 + 1][0] = r4[2]; bl[n2 * 2 + 1][1] = r4[3];
                    }
                    #pragma unroll
                    for (int mi = 0; mi < 2; mi++)
                        #pragma unroll
                        for (int ni = 0; ni < 8; ni++)
                            mma_bf16(acc[mi][ni], ah[mi], bl[ni]);
                }
            }
            __syncthreads();
        }

        // ---- fused lrelu + Wu2 partial for this j-tile ----
        #pragma unroll
        for (int mi = 0; mi < 2; mi++)
            #pragma unroll
            for (int ni = 0; ni < 8; ni++)
                #pragma unroll
                for (int e = 0; e < 4; e++) {
                    int j = j0 + warp_n * 64 + ni * 8 + (lane & 3) * 2 + (e & 1);
                    float h = acc[mi][ni][e] + sbu1[j];
                    h = (h >= 0.0f) ? h : 0.2f * h;
                    orow[mi * 2 + (e >> 1)] = fmaf(sWu2[j], h, orow[mi * 2 + (e >> 1)]);
                }
    }

    // reduce across the 4 lanes sharing a row (lane&3 = j-column subgroup)
    #pragma unroll
    for (int r4 = 0; r4 < 4; r4++) {
        float v = orow[r4];
        v += __shfl_xor_sync(0xffffffffu, v, 1);
        v += __shfl_xor_sync(0xffffffffu, v, 2);
        orow[r4] = v;
    }
    if ((lane & 3) == 0) {
        #pragma unroll
        for (int r4 = 0; r4 < 4; r4++) {
            int row = warp_m * 32 + (r4 >> 1) * 16 + (r4 & 1) * 8 + (lane >> 2);
            sRed[row * 2 + warp_n] = orow[r4];
        }
    }
    __syncthreads();
    if (tid < 128) {
        float s = sRed[tid * 2] + sRed[tid * 2 + 1] + __ldg(&bu2[0]);
        out[r0 + tid] = (s >= 0.0f) ? s : 0.2f * s;
    }
}

// =========================================================================
// launch
// =========================================================================
extern "C" void kernel_launch(void* const* d_in, const int* in_sizes, int n_in,
                              void* d_out, int out_size)
{
    const float* x       = (const float*)d_in[0];
    const float* coords1 = (const float*)d_in[1];
    const float* coords2 = (const float*)d_in[2];
    const float* g1      = (const float*)d_in[3];
    const float* be1     = (const float*)d_in[4];
    const float* Wq      = (const float*)d_in[5];
    const float* bq      = (const float*)d_in[6];
    const float* Wk      = (const float*)d_in[7];
    const float* bk      = (const float*)d_in[8];
    const float* Wv      = (const float*)d_in[9];
    const float* bv      = (const float*)d_in[10];
    const float* ls      = (const float*)d_in[11];
    const float* Wo      = (const float*)d_in[12];
    const float* bo      = (const float*)d_in[13];
    const float* Wp1     = (const float*)d_in[14];
    const float* bp1     = (const float*)d_in[15];
    const float* Wp2     = (const float*)d_in[16];
    const float* bp2     = (const float*)d_in[17];
    const float* g2      = (const float*)d_in[18];
    const float* be2     = (const float*)d_in[19];
    const float* Wn1     = (const float*)d_in[20];
    const float* bn1     = (const float*)d_in[21];
    const float* Wn2     = (const float*)d_in[22];
    const float* bn2     = (const float*)d_in[23];
    const float* g3      = (const float*)d_in[24];
    const float* be3     = (const float*)d_in[25];
    const float* Wu1     = (const float*)d_in[26];
    const float* bu1     = (const float*)d_in[27];
    const float* Wu2     = (const float*)d_in[28];
    const float* bu2     = (const float*)d_in[29];
    float* out = (float*)d_out;

    cudaFuncSetAttribute(k_attn, cudaFuncAttributeMaxDynamicSharedMemorySize,
                         SMEM_ATTN_BYTES);
    cudaFuncSetAttribute(k_head_mma, cudaFuncAttributeMaxDynamicSharedMemorySize,
                         HM_SMEM);

    k_ln1 <<<BT_ / 8, 256>>>(x, g1, be1);
    k_topk<<<T_ / 4, 128>>>(coords1, coords2);
    k_bias<<<T_, 256>>>(Wp1, bp1, Wp2, bp2);
    k_split<<<dim3(32, 32), 256>>>(Wu1);
    k_attn<<<296, 256, SMEM_ATTN_BYTES>>>(Wq, bq, Wk, bk, Wv, bv, ls, Wo, bo,
                                          g2, be2, Wn1, bn1, Wn2, bn2, g3, be3);
    k_head_mma<<<BT_ / 128, 256, HM_SMEM>>>(bu1, Wu2, bu2, out);
}